// round 5
// baseline (speedup 1.0000x reference)
#include <cuda_runtime.h>
#include <cuda_bf16.h>
#include <math.h>

// Problem dims (fixed by the reference)
#define NN 4096
#define DD 1024
#define GC1 1024
#define GC2 1024
#define FC1 512
#define NCLS 2
#define FW 8
#define BW 8

// ---------------- scratch (device globals; no dynamic allocation) ----------
__device__ float g_bufA[(size_t)NN * GC1];   // 16 MB
__device__ float g_bufB[(size_t)NN * GC1];   // 16 MB
__device__ float g_dinv[NN];
__device__ float g_pooled[GC2];

// ---------------- helpers ---------------------------------------------------
__device__ __forceinline__ float selu_f(float x) {
    const float scale = 1.0507009873554805f;
    const float alpha = 1.6732632423543772f;
    return x > 0.0f ? scale * x : scale * alpha * (expf(x) - 1.0f);
}

// ---------------- degree / normalization ------------------------------------
__global__ void degrees_kernel(const float* __restrict__ fw,
                               const float* __restrict__ bw,
                               float* __restrict__ dinv) {
    int i = blockIdx.x * blockDim.x + threadIdx.x;
    if (i >= NN) return;
    float d = 1.0f;
#pragma unroll
    for (int j = 0; j < FW; j++) if (i + j + 1 < NN) d += fw[j];
#pragma unroll
    for (int j = 0; j < BW; j++) if (i - j - 1 >= 0) d += bw[j];
    dinv[i] = 1.0f / sqrtf(d);
}

// ---------------- SGEMM: C[M,N] = A[M,K] @ B[K,N] + bias[N] -----------------
#define BM 128
#define BN 128
#define BK 8
#define TM 8
#define TN 8

__global__ __launch_bounds__(256)
void sgemm_bias_kernel(const float* __restrict__ A, const float* __restrict__ B,
                       const float* __restrict__ bias, float* __restrict__ C,
                       int M, int Nn, int K) {
    __shared__ float As[BK][BM];   // transposed A tile
    __shared__ float Bs[BK][BN];

    const int tid  = threadIdx.x;
    const int trow = tid / 16;          // 16 thread-rows
    const int tcol = tid % 16;          // 16 thread-cols

    // A tile load mapping: 128x8 floats = 256 float4 (one per thread)
    const int aRow = tid >> 1;          // 0..127
    const int aCol = (tid & 1) * 4;     // 0 or 4
    // B tile load mapping: 8x128 floats = 256 float4
    const int bRow = tid >> 5;          // 0..7
    const int bCol = (tid & 31) * 4;    // 0..124

    const float* Ab = A + (size_t)blockIdx.y * BM * K;
    const float* Bb = B + (size_t)blockIdx.x * BN;

    float acc[TM][TN] = {};

    for (int k0 = 0; k0 < K; k0 += BK) {
        float4 av = *(const float4*)(Ab + (size_t)aRow * K + k0 + aCol);
        As[aCol + 0][aRow] = av.x;
        As[aCol + 1][aRow] = av.y;
        As[aCol + 2][aRow] = av.z;
        As[aCol + 3][aRow] = av.w;
        *(float4*)(&Bs[bRow][bCol]) =
            *(const float4*)(Bb + (size_t)(k0 + bRow) * Nn + bCol);
        __syncthreads();

#pragma unroll
        for (int k = 0; k < BK; k++) {
            float ra[TM], rb[TN];
#pragma unroll
            for (int m = 0; m < TM; m++) ra[m] = As[k][trow * TM + m];
#pragma unroll
            for (int n = 0; n < TN; n++) rb[n] = Bs[k][tcol * TN + n];
#pragma unroll
            for (int m = 0; m < TM; m++)
#pragma unroll
                for (int n = 0; n < TN; n++)
                    acc[m][n] = fmaf(ra[m], rb[n], acc[m][n]);
        }
        __syncthreads();
    }

    // epilogue with bias
#pragma unroll
    for (int m = 0; m < TM; m++) {
        int row = blockIdx.y * BM + trow * TM + m;
#pragma unroll
        for (int n = 0; n < TN; n += 4) {
            int col = blockIdx.x * BN + tcol * TN + n;
            float4 bv = *(const float4*)(bias + col);
            float4 o;
            o.x = acc[m][n + 0] + bv.x;
            o.y = acc[m][n + 1] + bv.y;
            o.z = acc[m][n + 2] + bv.z;
            o.w = acc[m][n + 3] + bv.w;
            *(float4*)(C + (size_t)row * Nn + col) = o;
        }
    }
}

// ---------------- banded A-apply + SELU -------------------------------------
// out[i,:] = selu( sum_{offsets} w * dinv[i]*dinv[k] * H[k,:] )
__global__ __launch_bounds__(256)
void banded_selu_kernel(const float* __restrict__ H, float* __restrict__ out,
                        const float* __restrict__ fw, const float* __restrict__ bw,
                        const float* __restrict__ dinv) {
    const int i = blockIdx.x;            // row 0..N-1
    const int c = threadIdx.x * 4;       // 4 cols per thread, 256 threads -> 1024
    const float di = dinv[i];

    float4 h = *(const float4*)(H + (size_t)i * GC1 + c);
    float w0 = di * di;                  // self-loop weight 1 * dinv^2
    float4 acc = make_float4(h.x * w0, h.y * w0, h.z * w0, h.w * w0);

#pragma unroll
    for (int j = 0; j < FW; j++) {
        int k = i + j + 1;
        if (k < NN) {
            float w = fw[j] * di * dinv[k];
            float4 v = *(const float4*)(H + (size_t)k * GC1 + c);
            acc.x = fmaf(w, v.x, acc.x);
            acc.y = fmaf(w, v.y, acc.y);
            acc.z = fmaf(w, v.z, acc.z);
            acc.w = fmaf(w, v.w, acc.w);
        }
    }
#pragma unroll
    for (int j = 0; j < BW; j++) {
        int k = i - j - 1;
        if (k >= 0) {
            float w = bw[j] * di * dinv[k];
            float4 v = *(const float4*)(H + (size_t)k * GC1 + c);
            acc.x = fmaf(w, v.x, acc.x);
            acc.y = fmaf(w, v.y, acc.y);
            acc.z = fmaf(w, v.z, acc.z);
            acc.w = fmaf(w, v.w, acc.w);
        }
    }

    float4 o;
    o.x = selu_f(acc.x);
    o.y = selu_f(acc.y);
    o.z = selu_f(acc.z);
    o.w = selu_f(acc.w);
    *(float4*)(out + (size_t)i * GC1 + c) = o;
}

// ---------------- mean pool over rows ---------------------------------------
__global__ __launch_bounds__(256)
void meanpool_kernel(const float* __restrict__ H, float* __restrict__ pooled) {
    int c = blockIdx.x * blockDim.x + threadIdx.x;   // 0..1023
    float s0 = 0.f, s1 = 0.f, s2 = 0.f, s3 = 0.f;
    for (int i = 0; i < NN; i += 4) {
        s0 += H[(size_t)(i + 0) * GC2 + c];
        s1 += H[(size_t)(i + 1) * GC2 + c];
        s2 += H[(size_t)(i + 2) * GC2 + c];
        s3 += H[(size_t)(i + 3) * GC2 + c];
    }
    pooled[c] = ((s0 + s1) + (s2 + s3)) * (1.0f / NN);
}

// ---------------- FC head ----------------------------------------------------
__global__ __launch_bounds__(512)
void head_kernel(const float* __restrict__ pooled,
                 const float* __restrict__ w1, const float* __restrict__ b1,
                 const float* __restrict__ w2, const float* __restrict__ b2,
                 float* __restrict__ out) {
    __shared__ float z[FC1];
    __shared__ float p0s[64], p1s[64];
    int j = threadIdx.x;   // 0..511

    float s = b1[j];
    for (int c = 0; c < GC2; c++)
        s = fmaf(pooled[c], w1[(size_t)c * FC1 + j], s);
    z[j] = selu_f(s);
    __syncthreads();

    if (j < 64) {
        float a0 = 0.f, a1 = 0.f;
        for (int t = j; t < FC1; t += 64) {
            a0 = fmaf(z[t], w2[t * NCLS + 0], a0);
            a1 = fmaf(z[t], w2[t * NCLS + 1], a1);
        }
        p0s[j] = a0;
        p1s[j] = a1;
    }
    __syncthreads();

    if (j == 0) {
        float a0 = b2[0], a1 = b2[1];
        for (int t = 0; t < 64; t++) { a0 += p0s[t]; a1 += p1s[t]; }
        out[0] = a0;
        out[1] = a1;
    }
}

// ---------------- launch -----------------------------------------------------
extern "C" void kernel_launch(void* const* d_in, const int* in_sizes, int n_in,
                              void* d_out, int out_size) {
    const float* x     = (const float*)d_in[0];
    const float* fw_w  = (const float*)d_in[1];
    const float* bw_w  = (const float*)d_in[2];
    const float* gc_w1 = (const float*)d_in[3];
    const float* gc_b1 = (const float*)d_in[4];
    const float* gc_w2 = (const float*)d_in[5];
    const float* gc_b2 = (const float*)d_in[6];
    const float* fc_w1 = (const float*)d_in[7];
    const float* fc_b1 = (const float*)d_in[8];
    const float* fc_w2 = (const float*)d_in[9];
    const float* fc_b2 = (const float*)d_in[10];
    float* out = (float*)d_out;

    float *bufA, *bufB, *dinv, *pooled;
    cudaGetSymbolAddress((void**)&bufA,   g_bufA);
    cudaGetSymbolAddress((void**)&bufB,   g_bufB);
    cudaGetSymbolAddress((void**)&dinv,   g_dinv);
    cudaGetSymbolAddress((void**)&pooled, g_pooled);

    // 1. normalization factors
    degrees_kernel<<<(NN + 255) / 256, 256>>>(fw_w, bw_w, dinv);

    dim3 gemm_grid(GC1 / BN, NN / BM);   // (8, 32)

    // 2. H1 = x @ gc_w1 + b1
    sgemm_bias_kernel<<<gemm_grid, 256>>>(x, gc_w1, gc_b1, bufA, NN, GC1, DD);
    // 3. h1 = selu(A @ H1)
    banded_selu_kernel<<<NN, 256>>>(bufA, bufB, fw_w, bw_w, dinv);
    // 4. H2 = h1 @ gc_w2 + b2
    sgemm_bias_kernel<<<gemm_grid, 256>>>(bufB, gc_w2, gc_b2, bufA, NN, GC2, GC1);
    // 5. h2 = selu(A @ H2)
    banded_selu_kernel<<<NN, 256>>>(bufA, bufB, fw_w, bw_w, dinv);
    // 6. pooled = mean over rows
    meanpool_kernel<<<GC2 / 256, 256>>>(bufB, pooled);
    // 7. head
    head_kernel<<<1, FC1>>>(pooled, fc_w1, fc_b1, fc_w2, fc_b2, out);
}

// round 9
// speedup vs baseline: 2.7970x; 2.7970x over previous
#include <cuda_runtime.h>
#include <cuda_bf16.h>
#include <math.h>
#include <stdint.h>

// Problem dims (fixed by the reference)
#define NN 4096
#define DD 1024
#define GC1 1024
#define GC2 1024
#define FC1 512
#define NCLS 2
#define FW 8
#define BW 8

// ---------------- scratch (device globals; no dynamic allocation) ----------
__device__ float g_bufA[(size_t)NN * GC1];   // 16 MB
__device__ float g_bufB[(size_t)NN * GC1];   // 16 MB
__device__ float g_bufX[(size_t)NN * DD];    // 16 MB (tf32-rounded x)
__device__ float g_wT[(size_t)DD * GC1];     // 4 MB transposed+rounded weight
__device__ float g_dinv[NN];
__device__ float g_pooled[GC2];
__device__ float g_part[32 * GC2];
__device__ float g_zpart[16 * FC1];

// ---------------- helpers ---------------------------------------------------
__device__ __forceinline__ float selu_f(float x) {
    const float scale = 1.0507009873554805f;
    const float alpha = 1.6732632423543772f;
    return x > 0.0f ? scale * x : scale * alpha * (expf(x) - 1.0f);
}

__device__ __forceinline__ float to_tf32(float x) {
    float r;
    asm("cvt.rna.tf32.f32 %0, %1;" : "=f"(r) : "f"(x));
    return r;
}

__device__ __forceinline__ uint32_t smem_u32(const void* p) {
    uint32_t a;
    asm("{ .reg .u64 t; cvta.to.shared.u64 t, %1; cvt.u32.u64 %0, t; }"
        : "=r"(a) : "l"(p));
    return a;
}

// ---------------- degree / normalization ------------------------------------
__global__ void degrees_kernel(const float* __restrict__ fw,
                               const float* __restrict__ bw,
                               float* __restrict__ dinv) {
    int i = blockIdx.x * blockDim.x + threadIdx.x;
    if (i >= NN) return;
    float d = 1.0f;
#pragma unroll
    for (int j = 0; j < FW; j++) if (i + j + 1 < NN) d += fw[j];
#pragma unroll
    for (int j = 0; j < BW; j++) if (i - j - 1 >= 0) d += bw[j];
    dinv[i] = 1.0f / sqrtf(d);
}

// ---------------- tf32 rounding pre-pass ------------------------------------
__global__ __launch_bounds__(256)
void round_tf32_kernel(const float* __restrict__ in, float* __restrict__ out) {
    int i = (blockIdx.x * 256 + threadIdx.x) * 4;
    float4 v = *(const float4*)(in + i);
    v.x = to_tf32(v.x); v.y = to_tf32(v.y);
    v.z = to_tf32(v.z); v.w = to_tf32(v.w);
    *(float4*)(out + i) = v;
}

// ---------------- weight transpose (+tf32 round): WT[n][k] = W[k][n] --------
__global__ __launch_bounds__(256)
void transpose_kernel(const float* __restrict__ W, float* __restrict__ WT) {
    __shared__ float t[32][33];
    int bx = blockIdx.x * 32, by = blockIdx.y * 32;
    int tx = threadIdx.x % 32, ty4 = threadIdx.x / 32;   // 32 x 8
#pragma unroll
    for (int r = 0; r < 32; r += 8)
        t[ty4 + r][tx] = W[(size_t)(by + ty4 + r) * 1024 + bx + tx];
    __syncthreads();
#pragma unroll
    for (int r = 0; r < 32; r += 8)
        WT[(size_t)(bx + ty4 + r) * 1024 + by + tx] = to_tf32(t[tx][ty4 + r]);
}

// ---------------- tf32 mma.sync GEMM: C = A @ BT^T + bias -------------------
// A: [4096][1024] K-major (pre-rounded to tf32). BT: [1024 n][1024 k] rounded.
// CTA tile 128x128, BK=16, cp.async double buffer. 8 warps as 4(M) x 2(N),
// each warp 32x64 via m16n8k8 tf32 mma.sync.
#define BKG 16
#define PADR 20                     // floats per smem row (16 data + 4 pad)
#define TILE_F (128 * PADR)         // 2560 floats = 10240 B per tile buffer
#define NTG (1024 / BKG)            // 64 K-tiles

__global__ __launch_bounds__(256, 2)
void tf32_mma_gemm(const float* __restrict__ A, const float* __restrict__ BT,
                   const float* __restrict__ bias, float* __restrict__ C) {
    __shared__ float sA[2][TILE_F];
    __shared__ float sB[2][TILE_F];

    const int tid  = threadIdx.x;
    const int lane = tid & 31;
    const int wid  = tid >> 5;
    const int wm   = (wid & 3) * 32;    // warp M base within CTA tile
    const int wn   = (wid >> 2) * 64;   // warp N base within CTA tile

    const float* Ab = A  + (size_t)(blockIdx.y * 128) * 1024;
    const float* Bb = BT + (size_t)(blockIdx.x * 128) * 1024;

    // tile loader: 128 rows x 64B per operand; 512 16B chunks; 2 per thread
    auto load_tile = [&](int t, int b) {
        int k0 = t * BKG;
#pragma unroll
        for (int i = 0; i < 2; i++) {
            int q = tid + 256 * i;       // 0..511
            int row = q >> 2, c4 = q & 3;
            uint32_t da = smem_u32(&sA[b][row * PADR + c4 * 4]);
            asm volatile("cp.async.cg.shared.global [%0], [%1], 16;"
                         :: "r"(da), "l"(Ab + (size_t)row * 1024 + k0 + c4 * 4));
            uint32_t db = smem_u32(&sB[b][row * PADR + c4 * 4]);
            asm volatile("cp.async.cg.shared.global [%0], [%1], 16;"
                         :: "r"(db), "l"(Bb + (size_t)row * 1024 + k0 + c4 * 4));
        }
    };

    float acc[2][8][4];
#pragma unroll
    for (int mt = 0; mt < 2; mt++)
#pragma unroll
        for (int nt = 0; nt < 8; nt++)
#pragma unroll
            for (int i = 0; i < 4; i++) acc[mt][nt][i] = 0.0f;

    load_tile(0, 0);
    asm volatile("cp.async.commit_group;");

    const int r = lane >> 2;   // fragment row-group / n-group
    const int c = lane & 3;    // fragment k index within group

    for (int t = 0; t < NTG; t++) {
        if (t + 1 < NTG) {
            load_tile(t + 1, (t + 1) & 1);
            asm volatile("cp.async.commit_group;");
            asm volatile("cp.async.wait_group 1;");
        } else {
            asm volatile("cp.async.wait_group 0;");
        }
        __syncthreads();

        const float* pa = sA[t & 1];
        const float* pb = sB[t & 1];
#pragma unroll
        for (int kk = 0; kk < BKG; kk += 8) {
            uint32_t af[2][4], bf[8][2];
#pragma unroll
            for (int mt = 0; mt < 2; mt++) {
                int base = (wm + mt * 16 + r) * PADR + kk + c;
                af[mt][0] = __float_as_uint(pa[base]);
                af[mt][1] = __float_as_uint(pa[base + 8 * PADR]);
                af[mt][2] = __float_as_uint(pa[base + 4]);
                af[mt][3] = __float_as_uint(pa[base + 8 * PADR + 4]);
            }
#pragma unroll
            for (int nt = 0; nt < 8; nt++) {
                int base = (wn + nt * 8 + r) * PADR + kk + c;
                bf[nt][0] = __float_as_uint(pb[base]);
                bf[nt][1] = __float_as_uint(pb[base + 4]);
            }
#pragma unroll
            for (int mt = 0; mt < 2; mt++)
#pragma unroll
                for (int nt = 0; nt < 8; nt++)
                    asm volatile(
                        "mma.sync.aligned.m16n8k8.row.col.f32.tf32.tf32.f32 "
                        "{%0,%1,%2,%3}, {%4,%5,%6,%7}, {%8,%9}, {%0,%1,%2,%3};"
                        : "+f"(acc[mt][nt][0]), "+f"(acc[mt][nt][1]),
                          "+f"(acc[mt][nt][2]), "+f"(acc[mt][nt][3])
                        : "r"(af[mt][0]), "r"(af[mt][1]), "r"(af[mt][2]), "r"(af[mt][3]),
                          "r"(bf[nt][0]), "r"(bf[nt][1]));
        }
        __syncthreads();
    }

    // epilogue: direct register -> gmem with bias (float2 stores)
    const int gRow = blockIdx.y * 128 + wm;
    const int gCol = blockIdx.x * 128 + wn;
#pragma unroll
    for (int nt = 0; nt < 8; nt++) {
        int col = gCol + nt * 8 + 2 * c;
        float2 bv = *(const float2*)(bias + col);
#pragma unroll
        for (int mt = 0; mt < 2; mt++) {
            int row = gRow + mt * 16 + r;
            float2 o0 = make_float2(acc[mt][nt][0] + bv.x, acc[mt][nt][1] + bv.y);
            *(float2*)(C + (size_t)row * 1024 + col) = o0;
            float2 o1 = make_float2(acc[mt][nt][2] + bv.x, acc[mt][nt][3] + bv.y);
            *(float2*)(C + (size_t)(row + 8) * 1024 + col) = o1;
        }
    }
}

// ---------------- banded A-apply + SELU (optional tf32 round of output) -----
__global__ __launch_bounds__(256)
void banded_selu_kernel(const float* __restrict__ H, float* __restrict__ out,
                        const float* __restrict__ fw, const float* __restrict__ bw,
                        const float* __restrict__ dinv, int round_out) {
    const int i = blockIdx.x;
    const int c = threadIdx.x * 4;
    const float di = dinv[i];

    float4 h = *(const float4*)(H + (size_t)i * GC1 + c);
    float w0 = di * di;
    float4 acc = make_float4(h.x * w0, h.y * w0, h.z * w0, h.w * w0);

#pragma unroll
    for (int j = 0; j < FW; j++) {
        int k = i + j + 1;
        if (k < NN) {
            float w = fw[j] * di * dinv[k];
            float4 v = *(const float4*)(H + (size_t)k * GC1 + c);
            acc.x = fmaf(w, v.x, acc.x); acc.y = fmaf(w, v.y, acc.y);
            acc.z = fmaf(w, v.z, acc.z); acc.w = fmaf(w, v.w, acc.w);
        }
    }
#pragma unroll
    for (int j = 0; j < BW; j++) {
        int k = i - j - 1;
        if (k >= 0) {
            float w = bw[j] * di * dinv[k];
            float4 v = *(const float4*)(H + (size_t)k * GC1 + c);
            acc.x = fmaf(w, v.x, acc.x); acc.y = fmaf(w, v.y, acc.y);
            acc.z = fmaf(w, v.z, acc.z); acc.w = fmaf(w, v.w, acc.w);
        }
    }

    float4 o;
    o.x = selu_f(acc.x); o.y = selu_f(acc.y);
    o.z = selu_f(acc.z); o.w = selu_f(acc.w);
    if (round_out) {
        o.x = to_tf32(o.x); o.y = to_tf32(o.y);
        o.z = to_tf32(o.z); o.w = to_tf32(o.w);
    }
    *(float4*)(out + (size_t)i * GC1 + c) = o;
}

// ---------------- mean pool: 2-stage ----------------------------------------
__global__ __launch_bounds__(256)
void meanpool1_kernel(const float* __restrict__ H, float* __restrict__ part) {
    int col = blockIdx.y * 256 + threadIdx.x;
    int r0 = blockIdx.x * 128;
    float s = 0.f;
    for (int i = 0; i < 128; i++)
        s += H[(size_t)(r0 + i) * GC2 + col];
    part[blockIdx.x * GC2 + col] = s;
}

__global__ __launch_bounds__(256)
void meanpool2_kernel(const float* __restrict__ part, float* __restrict__ pooled) {
    int col = blockIdx.x * 256 + threadIdx.x;
    float s = 0.f;
#pragma unroll
    for (int p = 0; p < 32; p++)
        s += part[p * GC2 + col];
    pooled[col] = s * (1.0f / NN);
}

// ---------------- FC head: split-K partials + reduce -------------------------
__global__ __launch_bounds__(512)
void head1_kernel(const float* __restrict__ pooled, const float* __restrict__ w1,
                  float* __restrict__ zpart) {
    int j = threadIdx.x;
    int c0 = blockIdx.x * 64;
    float s = 0.f;
#pragma unroll 8
    for (int c = 0; c < 64; c++)
        s = fmaf(pooled[c0 + c], w1[(size_t)(c0 + c) * FC1 + j], s);
    zpart[blockIdx.x * FC1 + j] = s;
}

__global__ __launch_bounds__(512)
void head2_kernel(const float* __restrict__ zpart,
                  const float* __restrict__ b1,
                  const float* __restrict__ w2, const float* __restrict__ b2,
                  float* __restrict__ out) {
    __shared__ float z[FC1];
    __shared__ float p0s[64], p1s[64];
    int j = threadIdx.x;

    float s = b1[j];
#pragma unroll
    for (int b = 0; b < 16; b++)
        s += zpart[b * FC1 + j];
    z[j] = selu_f(s);
    __syncthreads();

    if (j < 64) {
        float a0 = 0.f, a1 = 0.f;
        for (int t = j; t < FC1; t += 64) {
            a0 = fmaf(z[t], w2[t * NCLS + 0], a0);
            a1 = fmaf(z[t], w2[t * NCLS + 1], a1);
        }
        p0s[j] = a0; p1s[j] = a1;
    }
    __syncthreads();

    if (j == 0) {
        float a0 = b2[0], a1 = b2[1];
        for (int t = 0; t < 64; t++) { a0 += p0s[t]; a1 += p1s[t]; }
        out[0] = a0; out[1] = a1;
    }
}

// ---------------- launch -----------------------------------------------------
extern "C" void kernel_launch(void* const* d_in, const int* in_sizes, int n_in,
                              void* d_out, int out_size) {
    const float* x     = (const float*)d_in[0];
    const float* fw_w  = (const float*)d_in[1];
    const float* bw_w  = (const float*)d_in[2];
    const float* gc_w1 = (const float*)d_in[3];
    const float* gc_b1 = (const float*)d_in[4];
    const float* gc_w2 = (const float*)d_in[5];
    const float* gc_b2 = (const float*)d_in[6];
    const float* fc_w1 = (const float*)d_in[7];
    const float* fc_b1 = (const float*)d_in[8];
    const float* fc_w2 = (const float*)d_in[9];
    const float* fc_b2 = (const float*)d_in[10];
    float* out = (float*)d_out;

    float *bufA, *bufB, *bufX, *wT, *dinv, *pooled, *part, *zpart;
    cudaGetSymbolAddress((void**)&bufA,   g_bufA);
    cudaGetSymbolAddress((void**)&bufB,   g_bufB);
    cudaGetSymbolAddress((void**)&bufX,   g_bufX);
    cudaGetSymbolAddress((void**)&wT,     g_wT);
    cudaGetSymbolAddress((void**)&dinv,   g_dinv);
    cudaGetSymbolAddress((void**)&pooled, g_pooled);
    cudaGetSymbolAddress((void**)&part,   g_part);
    cudaGetSymbolAddress((void**)&zpart,  g_zpart);

    degrees_kernel<<<(NN + 255) / 256, 256>>>(fw_w, bw_w, dinv);

    dim3 tgrid(32, 32);
    dim3 ggrid(GC1 / 128, NN / 128);   // (8, 32)

    // tf32-round x once
    round_tf32_kernel<<<(NN * DD) / 1024, 256>>>(x, bufX);

    // layer 1
    transpose_kernel<<<tgrid, 256>>>(gc_w1, wT);
    tf32_mma_gemm<<<ggrid, 256>>>(bufX, wT, gc_b1, bufA);
    banded_selu_kernel<<<NN, 256>>>(bufA, bufB, fw_w, bw_w, dinv, 1);

    // layer 2
    transpose_kernel<<<tgrid, 256>>>(gc_w2, wT);
    tf32_mma_gemm<<<ggrid, 256>>>(bufB, wT, gc_b2, bufA);
    banded_selu_kernel<<<NN, 256>>>(bufA, bufB, fw_w, bw_w, dinv, 0);

    // pool + head
    meanpool1_kernel<<<dim3(32, 4), 256>>>(bufB, part);
    meanpool2_kernel<<<4, 256>>>(part, pooled);
    head1_kernel<<<16, FC1>>>(pooled, fc_w1, zpart);
    head2_kernel<<<1, FC1>>>(zpart, fc_b1, fc_w2, fc_b2, out);
}

// round 10
// speedup vs baseline: 3.4131x; 1.2203x over previous
#include <cuda_runtime.h>
#include <cuda_bf16.h>
#include <math.h>
#include <stdint.h>

// Problem dims (fixed by the reference)
#define NN 4096
#define DD 1024
#define GC1 1024
#define GC2 1024
#define FC1 512
#define NCLS 2
#define FW 8
#define BW 8

// ---------------- scratch (device globals; no dynamic allocation) ----------
__device__ float g_bufA[(size_t)NN * GC1];   // 16 MB
__device__ float g_bufB[(size_t)NN * GC1];   // 16 MB
__device__ float g_bufX[(size_t)NN * DD];    // 16 MB (tf32-rounded x)
__device__ float g_wT[(size_t)DD * GC1];     // 4 MB transposed+rounded weight
__device__ float g_dinv[NN];
__device__ float g_pooled[GC2];
__device__ float g_part[128 * GC2];          // banded-pool partials (512 KB)
__device__ float g_zpart[16 * FC1];

// ---------------- helpers ---------------------------------------------------
__device__ __forceinline__ float selu_f(float x) {
    const float scale = 1.0507009873554805f;
    const float alpha = 1.6732632423543772f;
    return x > 0.0f ? scale * x : scale * alpha * (expf(x) - 1.0f);
}

__device__ __forceinline__ float to_tf32(float x) {
    float r;
    asm("cvt.rna.tf32.f32 %0, %1;" : "=f"(r) : "f"(x));
    return r;
}

__device__ __forceinline__ uint32_t smem_u32(const void* p) {
    uint32_t a;
    asm("{ .reg .u64 t; cvta.to.shared.u64 t, %1; cvt.u32.u64 %0, t; }"
        : "=r"(a) : "l"(p));
    return a;
}

// ---------------- degree / normalization ------------------------------------
__global__ void degrees_kernel(const float* __restrict__ fw,
                               const float* __restrict__ bw,
                               float* __restrict__ dinv) {
    int i = blockIdx.x * blockDim.x + threadIdx.x;
    if (i >= NN) return;
    float d = 1.0f;
#pragma unroll
    for (int j = 0; j < FW; j++) if (i + j + 1 < NN) d += fw[j];
#pragma unroll
    for (int j = 0; j < BW; j++) if (i - j - 1 >= 0) d += bw[j];
    dinv[i] = 1.0f / sqrtf(d);
}

// ---------------- tf32 rounding pre-pass ------------------------------------
__global__ __launch_bounds__(256)
void round_tf32_kernel(const float* __restrict__ in, float* __restrict__ out) {
    int i = (blockIdx.x * 256 + threadIdx.x) * 4;
    float4 v = *(const float4*)(in + i);
    v.x = to_tf32(v.x); v.y = to_tf32(v.y);
    v.z = to_tf32(v.z); v.w = to_tf32(v.w);
    *(float4*)(out + i) = v;
}

// ---------------- weight transpose (+tf32 round): WT[n][k] = W[k][n] --------
__global__ __launch_bounds__(256)
void transpose_kernel(const float* __restrict__ W, float* __restrict__ WT) {
    __shared__ float t[32][33];
    int bx = blockIdx.x * 32, by = blockIdx.y * 32;
    int tx = threadIdx.x % 32, ty4 = threadIdx.x / 32;   // 32 x 8
#pragma unroll
    for (int r = 0; r < 32; r += 8)
        t[ty4 + r][tx] = W[(size_t)(by + ty4 + r) * 1024 + bx + tx];
    __syncthreads();
#pragma unroll
    for (int r = 0; r < 32; r += 8)
        WT[(size_t)(bx + ty4 + r) * 1024 + by + tx] = to_tf32(t[tx][ty4 + r]);
}

// ---------------- tf32 mma.sync GEMM: C = A @ BT^T + bias -------------------
// CTA 128x128, 128 threads (4 warps 2x2), warp tile 64x64 (mt=4, nt=8).
// BK=16, 3-stage cp.async pipeline, smem rows padded to 20 floats.
#define BKG 16
#define PADR 20
#define TILE_F (128 * PADR)               // 2560 floats per operand tile
#define STAGE_B (2 * TILE_F * 4)          // 20480 bytes per stage (A+B)
#define GEMM_SMEM (3 * STAGE_B)           // 61440 bytes
#define NTG (1024 / BKG)                  // 64 K-tiles

__global__ __launch_bounds__(128, 2)
void tf32_mma_gemm(const float* __restrict__ A, const float* __restrict__ BT,
                   const float* __restrict__ bias, float* __restrict__ C) {
    extern __shared__ __align__(16) float smem[];

    const int tid  = threadIdx.x;
    const int lane = tid & 31;
    const int wid  = tid >> 5;
    const int wm   = (wid & 1) * 64;    // warp M base
    const int wn   = (wid >> 1) * 64;   // warp N base

    const float* Ab = A  + (size_t)(blockIdx.y * 128) * 1024;
    const float* Bb = BT + (size_t)(blockIdx.x * 128) * 1024;

    // loader: per stage A=512 + B=512 float4 chunks, 8 per thread
    auto load_tile = [&](int t, int s) {
        float* sA = smem + s * (2 * TILE_F);
        float* sB = sA + TILE_F;
        int k0 = t * BKG;
#pragma unroll
        for (int i = 0; i < 4; i++) {
            int q = tid + 128 * i;            // 0..511
            int row = q >> 2, c4 = q & 3;
            uint32_t da = smem_u32(&sA[row * PADR + c4 * 4]);
            asm volatile("cp.async.cg.shared.global [%0], [%1], 16;"
                         :: "r"(da), "l"(Ab + (size_t)row * 1024 + k0 + c4 * 4));
            uint32_t db = smem_u32(&sB[row * PADR + c4 * 4]);
            asm volatile("cp.async.cg.shared.global [%0], [%1], 16;"
                         :: "r"(db), "l"(Bb + (size_t)row * 1024 + k0 + c4 * 4));
        }
    };

    float acc[4][8][4];
#pragma unroll
    for (int mt = 0; mt < 4; mt++)
#pragma unroll
        for (int nt = 0; nt < 8; nt++)
#pragma unroll
            for (int i = 0; i < 4; i++) acc[mt][nt][i] = 0.0f;

    load_tile(0, 0);
    asm volatile("cp.async.commit_group;");
    load_tile(1, 1);
    asm volatile("cp.async.commit_group;");

    const int r = lane >> 2;
    const int c = lane & 3;

    for (int t = 0; t < NTG; t++) {
        if (t + 2 < NTG) load_tile(t + 2, (t + 2) % 3);
        asm volatile("cp.async.commit_group;");
        asm volatile("cp.async.wait_group 2;");
        __syncthreads();

        const float* pa = smem + (t % 3) * (2 * TILE_F);
        const float* pb = pa + TILE_F;
#pragma unroll
        for (int kk = 0; kk < BKG; kk += 8) {
            uint32_t af[4][4], bf[8][2];
#pragma unroll
            for (int mt = 0; mt < 4; mt++) {
                int base = (wm + mt * 16 + r) * PADR + kk + c;
                af[mt][0] = __float_as_uint(pa[base]);
                af[mt][1] = __float_as_uint(pa[base + 8 * PADR]);
                af[mt][2] = __float_as_uint(pa[base + 4]);
                af[mt][3] = __float_as_uint(pa[base + 8 * PADR + 4]);
            }
#pragma unroll
            for (int nt = 0; nt < 8; nt++) {
                int base = (wn + nt * 8 + r) * PADR + kk + c;
                bf[nt][0] = __float_as_uint(pb[base]);
                bf[nt][1] = __float_as_uint(pb[base + 4]);
            }
#pragma unroll
            for (int mt = 0; mt < 4; mt++)
#pragma unroll
                for (int nt = 0; nt < 8; nt++)
                    asm volatile(
                        "mma.sync.aligned.m16n8k8.row.col.f32.tf32.tf32.f32 "
                        "{%0,%1,%2,%3}, {%4,%5,%6,%7}, {%8,%9}, {%0,%1,%2,%3};"
                        : "+f"(acc[mt][nt][0]), "+f"(acc[mt][nt][1]),
                          "+f"(acc[mt][nt][2]), "+f"(acc[mt][nt][3])
                        : "r"(af[mt][0]), "r"(af[mt][1]), "r"(af[mt][2]), "r"(af[mt][3]),
                          "r"(bf[nt][0]), "r"(bf[nt][1]));
        }
        __syncthreads();
    }

    // epilogue: register -> gmem with bias
    const int gRow = blockIdx.y * 128 + wm;
    const int gCol = blockIdx.x * 128 + wn;
#pragma unroll
    for (int nt = 0; nt < 8; nt++) {
        int col = gCol + nt * 8 + 2 * c;
        float2 bv = *(const float2*)(bias + col);
#pragma unroll
        for (int mt = 0; mt < 4; mt++) {
            int row = gRow + mt * 16 + r;
            float2 o0 = make_float2(acc[mt][nt][0] + bv.x, acc[mt][nt][1] + bv.y);
            *(float2*)(C + (size_t)row * 1024 + col) = o0;
            float2 o1 = make_float2(acc[mt][nt][2] + bv.x, acc[mt][nt][3] + bv.y);
            *(float2*)(C + (size_t)(row + 8) * 1024 + col) = o1;
        }
    }
}

// ---------------- banded A-apply + SELU, sliding window ----------------------
// Each thread: one column, 32 output rows, 48-row register window pre-scaled
// by dinv[k]. MODE 0: store selu (optionally tf32-rounded). MODE 1: emit
// per-tile column partial sums only (for mean pool), no H store.
template <int MODE, int ROUND>
__global__ __launch_bounds__(256)
void banded_win_kernel(const float* __restrict__ H, float* __restrict__ out,
                       const float* __restrict__ fw, const float* __restrict__ bw,
                       const float* __restrict__ dinv) {
    __shared__ float sdv[48];
    __shared__ float scf[FW], scb[BW];
    const int tid = threadIdx.x;
    const int col = blockIdx.y * 256 + tid;
    const int r0  = blockIdx.x * 32;

    if (tid < 48) {
        int row = r0 - 8 + tid;
        sdv[tid] = (row >= 0 && row < NN) ? dinv[row] : 0.0f;
    } else if (tid < 56) scf[tid - 48] = fw[tid - 48];
    else if (tid < 64)   scb[tid - 56] = bw[tid - 56];
    __syncthreads();

    float hs[48];
#pragma unroll
    for (int w = 0; w < 48; w++) {
        int row = r0 - 8 + w;
        hs[w] = (row >= 0 && row < NN)
              ? H[(size_t)row * GC1 + col] * sdv[w] : 0.0f;
    }

    float psum = 0.0f;
#pragma unroll
    for (int i = 0; i < 32; i++) {
        float acc = hs[i + 8];
#pragma unroll
        for (int j = 1; j <= 8; j++) {
            acc = fmaf(scf[j - 1], hs[i + 8 + j], acc);
            acc = fmaf(scb[j - 1], hs[i + 8 - j], acc);
        }
        float v = selu_f(sdv[i + 8] * acc);
        if (MODE == 0) {
            if (ROUND) v = to_tf32(v);
            out[(size_t)(r0 + i) * GC1 + col] = v;
        } else {
            psum += v;
        }
    }
    if (MODE == 1)
        out[(size_t)blockIdx.x * GC1 + col] = psum;   // out = g_part
}

// ---------------- pool reduce (128 partials) ---------------------------------
__global__ __launch_bounds__(256)
void meanpool2_kernel(const float* __restrict__ part, float* __restrict__ pooled) {
    int col = blockIdx.x * 256 + threadIdx.x;
    float s = 0.f;
#pragma unroll 8
    for (int p = 0; p < 128; p++)
        s += part[(size_t)p * GC2 + col];
    pooled[col] = s * (1.0f / NN);
}

// ---------------- FC head: split-K partials + reduce -------------------------
__global__ __launch_bounds__(512)
void head1_kernel(const float* __restrict__ pooled, const float* __restrict__ w1,
                  float* __restrict__ zpart) {
    int j = threadIdx.x;
    int c0 = blockIdx.x * 64;
    float s = 0.f;
#pragma unroll 8
    for (int c = 0; c < 64; c++)
        s = fmaf(pooled[c0 + c], w1[(size_t)(c0 + c) * FC1 + j], s);
    zpart[blockIdx.x * FC1 + j] = s;
}

__global__ __launch_bounds__(512)
void head2_kernel(const float* __restrict__ zpart,
                  const float* __restrict__ b1,
                  const float* __restrict__ w2, const float* __restrict__ b2,
                  float* __restrict__ out) {
    __shared__ float z[FC1];
    __shared__ float p0s[64], p1s[64];
    int j = threadIdx.x;

    float s = b1[j];
#pragma unroll
    for (int b = 0; b < 16; b++)
        s += zpart[b * FC1 + j];
    z[j] = selu_f(s);
    __syncthreads();

    if (j < 64) {
        float a0 = 0.f, a1 = 0.f;
        for (int t = j; t < FC1; t += 64) {
            a0 = fmaf(z[t], w2[t * NCLS + 0], a0);
            a1 = fmaf(z[t], w2[t * NCLS + 1], a1);
        }
        p0s[j] = a0; p1s[j] = a1;
    }
    __syncthreads();

    if (j == 0) {
        float a0 = b2[0], a1 = b2[1];
        for (int t = 0; t < 64; t++) { a0 += p0s[t]; a1 += p1s[t]; }
        out[0] = a0; out[1] = a1;
    }
}

// ---------------- launch -----------------------------------------------------
extern "C" void kernel_launch(void* const* d_in, const int* in_sizes, int n_in,
                              void* d_out, int out_size) {
    const float* x     = (const float*)d_in[0];
    const float* fw_w  = (const float*)d_in[1];
    const float* bw_w  = (const float*)d_in[2];
    const float* gc_w1 = (const float*)d_in[3];
    const float* gc_b1 = (const float*)d_in[4];
    const float* gc_w2 = (const float*)d_in[5];
    const float* gc_b2 = (const float*)d_in[6];
    const float* fc_w1 = (const float*)d_in[7];
    const float* fc_b1 = (const float*)d_in[8];
    const float* fc_w2 = (const float*)d_in[9];
    const float* fc_b2 = (const float*)d_in[10];
    float* out = (float*)d_out;

    float *bufA, *bufB, *bufX, *wT, *dinv, *pooled, *part, *zpart;
    cudaGetSymbolAddress((void**)&bufA,   g_bufA);
    cudaGetSymbolAddress((void**)&bufB,   g_bufB);
    cudaGetSymbolAddress((void**)&bufX,   g_bufX);
    cudaGetSymbolAddress((void**)&wT,     g_wT);
    cudaGetSymbolAddress((void**)&dinv,   g_dinv);
    cudaGetSymbolAddress((void**)&pooled, g_pooled);
    cudaGetSymbolAddress((void**)&part,   g_part);
    cudaGetSymbolAddress((void**)&zpart,  g_zpart);

    cudaFuncSetAttribute(tf32_mma_gemm,
                         cudaFuncAttributeMaxDynamicSharedMemorySize, GEMM_SMEM);

    degrees_kernel<<<(NN + 255) / 256, 256>>>(fw_w, bw_w, dinv);

    dim3 tgrid(32, 32);
    dim3 ggrid(GC1 / 128, NN / 128);     // (8, 32)
    dim3 bgrid(NN / 32, GC1 / 256);      // (128, 4)

    round_tf32_kernel<<<(NN * DD) / 1024, 256>>>(x, bufX);

    // layer 1
    transpose_kernel<<<tgrid, 256>>>(gc_w1, wT);
    tf32_mma_gemm<<<ggrid, 128, GEMM_SMEM>>>(bufX, wT, gc_b1, bufA);
    banded_win_kernel<0, 1><<<bgrid, 256>>>(bufA, bufB, fw_w, bw_w, dinv);

    // layer 2 (banded output fused into pool partials)
    transpose_kernel<<<tgrid, 256>>>(gc_w2, wT);
    tf32_mma_gemm<<<ggrid, 128, GEMM_SMEM>>>(bufB, wT, gc_b2, bufA);
    banded_win_kernel<1, 0><<<bgrid, 256>>>(bufA, part, fw_w, bw_w, dinv);

    // pool + head
    meanpool2_kernel<<<4, 256>>>(part, pooled);
    head1_kernel<<<16, FC1>>>(pooled, fc_w1, zpart);
    head2_kernel<<<1, FC1>>>(zpart, fc_b1, fc_w2, fc_b2, out);
}

// round 11
// speedup vs baseline: 3.6950x; 1.0826x over previous
#include <cuda_runtime.h>
#include <cuda_bf16.h>
#include <math.h>
#include <stdint.h>

// Problem dims (fixed by the reference)
#define NN 4096
#define DD 1024
#define GC1 1024
#define GC2 1024
#define FC1 512
#define NCLS 2
#define FW 8
#define BW 8

// ---------------- scratch (device globals; no dynamic allocation) ----------
__device__ float g_bufA[(size_t)NN * GC1];   // 16 MB  (GEMM C, normal layout)
__device__ float g_bufB[(size_t)NN * GC1];   // 16 MB  (permuted A-operand for GEMM2)
__device__ float g_bufX[(size_t)NN * DD];    // 16 MB  (permuted+rounded x)
__device__ float g_wT[(size_t)DD * GC1];     // 4 MB   (permuted+rounded weight)
__device__ float g_dinv[NN];
__device__ float g_pooled[GC2];
__device__ float g_part[128 * GC2];
__device__ float g_zpart[16 * FC1];

// ---------------- helpers ---------------------------------------------------
__device__ __forceinline__ float selu_f(float x) {
    const float scale = 1.0507009873554805f;
    const float alpha = 1.6732632423543772f;
    return x > 0.0f ? scale * x : scale * alpha * (expf(x) - 1.0f);
}

__device__ __forceinline__ float to_tf32(float x) {
    float r;
    asm("cvt.rna.tf32.f32 %0, %1;" : "=f"(r) : "f"(x));
    return r;
}

__device__ __forceinline__ uint32_t smem_u32(const void* p) {
    uint32_t a;
    asm("{ .reg .u64 t; cvta.to.shared.u64 t, %1; cvt.u32.u64 %0, t; }"
        : "=r"(a) : "l"(p));
    return a;
}

// Permuted layout (K = 1024 fixed -> 128 K8-blocks per row-block):
// 16x8 blocks; lane (r=0..7, c=0..3) owns float4
// { M[R*16+r][K8*8+c], M[R*16+r+8][..c], M[R*16+r][..c+4], M[R*16+r+8][..c+4] }
// float index:
__device__ __forceinline__ size_t perm_fidx(int row, int k) {
    int R = row >> 4, rr = row & 15;
    int K8 = k >> 3, cc = k & 7;
    int lane = ((rr & 7) << 2) | (cc & 3);
    int j = (rr >> 3) | ((cc >> 2) << 1);
    return ((((size_t)R * 128 + K8) * 32 + lane) << 2) + j;
}

// ---------------- degree / normalization ------------------------------------
__global__ void degrees_kernel(const float* __restrict__ fw,
                               const float* __restrict__ bw,
                               float* __restrict__ dinv) {
    int i = blockIdx.x * blockDim.x + threadIdx.x;
    if (i >= NN) return;
    float d = 1.0f;
#pragma unroll
    for (int j = 0; j < FW; j++) if (i + j + 1 < NN) d += fw[j];
#pragma unroll
    for (int j = 0; j < BW; j++) if (i - j - 1 >= 0) d += bw[j];
    dinv[i] = 1.0f / sqrtf(d);
}

// ---------------- X: round + permute ----------------------------------------
// one thread = one 16B output group; coalesced float4 stores
__global__ __launch_bounds__(256)
void permX_kernel(const float* __restrict__ in, float* __restrict__ out) {
    int g = blockIdx.x * 256 + threadIdx.x;   // 0 .. 1048575
    int lane = g & 31;
    int K8 = (g >> 5) & 127;
    int R = g >> 12;
    int r = lane >> 2, c = lane & 3;
    int row = R * 16 + r, k = K8 * 8 + c;
    float4 v;
    v.x = to_tf32(in[(size_t)row * 1024 + k]);
    v.y = to_tf32(in[(size_t)(row + 8) * 1024 + k]);
    v.z = to_tf32(in[(size_t)row * 1024 + k + 4]);
    v.w = to_tf32(in[(size_t)(row + 8) * 1024 + k + 4]);
    ((float4*)out)[g] = v;
}

// ---------------- W: transpose + round + permute -----------------------------
// B_perm over (n-rowblocks, k): value = W[k][n]
__global__ __launch_bounds__(256)
void permW_kernel(const float* __restrict__ W, float* __restrict__ out) {
    __shared__ float t[32][33];
    int bx = blockIdx.x * 32, by = blockIdx.y * 32;  // bx: n base, by: k base
    int tx = threadIdx.x % 32, ty = threadIdx.x / 32;
#pragma unroll
    for (int r = 0; r < 32; r += 8)
        t[ty + r][tx] = W[(size_t)(by + ty + r) * 1024 + bx + tx];   // t[k][n]
    __syncthreads();

    int tid = threadIdx.x;
    int lane = tid & 31;
    int K8l = (tid >> 5) & 3;
    int N16l = tid >> 7;
    int r = lane >> 2, c = lane & 3;
    int nl = N16l * 16 + r;
    int kl = K8l * 8 + c;
    float4 v;
    v.x = to_tf32(t[kl][nl]);
    v.y = to_tf32(t[kl][nl + 8]);
    v.z = to_tf32(t[kl + 4][nl]);
    v.w = to_tf32(t[kl + 4][nl + 8]);
    size_t gidx = (((size_t)(bx / 16 + N16l) * 128) + (by / 8 + K8l)) * 32 + lane;
    ((float4*)out)[gidx] = v;
}

// ---------------- tf32 mma.sync GEMM: C = A @ BT^T + bias -------------------
// Operands pre-permuted. CTA 128x128, 128 threads (4 warps 2x2),
// warp tile 64x64. BK=16, 3-stage cp.async, single sync per iter.
#define TILEPF 2048                        // floats per operand tile (8 KB)
#define GEMM_SMEM (3 * 2 * TILEPF * 4)     // 49152 B
#define NTG 64

__global__ __launch_bounds__(128, 2)
void tf32_mma_gemm(const float* __restrict__ A, const float* __restrict__ BT,
                   const float* __restrict__ bias, float* __restrict__ C) {
    extern __shared__ __align__(16) float smem[];

    const int tid  = threadIdx.x;
    const int lane = tid & 31;
    const int wid  = tid >> 5;
    const int wmB  = (wid & 1) * 4;     // warp M base in 16-row blocks
    const int wnB  = (wid >> 1) * 4;    // warp N base in 16-col blocks

    const float4* gA = (const float4*)A  + (size_t)blockIdx.y * 8 * 4096;
    const float4* gB = (const float4*)BT + (size_t)blockIdx.x * 8 * 4096;

    auto load_tile = [&](int t, int s) {
        float4* sA = (float4*)(smem + s * (2 * TILEPF));
        float4* sB = sA + 512;
        const float4* ga = gA + t * 64;
        const float4* gb = gB + t * 64;
#pragma unroll
        for (int i = 0; i < 4; i++) {
            int q = tid + 128 * i;              // 0..511
            int Rl = q >> 6, rem = q & 63;
            uint32_t da = smem_u32(sA + q);
            asm volatile("cp.async.cg.shared.global [%0], [%1], 16;"
                         :: "r"(da), "l"(ga + (size_t)Rl * 4096 + rem));
            uint32_t db = smem_u32(sB + q);
            asm volatile("cp.async.cg.shared.global [%0], [%1], 16;"
                         :: "r"(db), "l"(gb + (size_t)Rl * 4096 + rem));
        }
    };

    float acc[4][8][4];
#pragma unroll
    for (int mt = 0; mt < 4; mt++)
#pragma unroll
        for (int nt = 0; nt < 8; nt++)
#pragma unroll
            for (int i = 0; i < 4; i++) acc[mt][nt][i] = 0.0f;

    load_tile(0, 0);
    asm volatile("cp.async.commit_group;");
    load_tile(1, 1);
    asm volatile("cp.async.commit_group;");

    for (int t = 0; t < NTG; t++) {
        asm volatile("cp.async.wait_group 1;");
        __syncthreads();
        if (t + 2 < NTG) load_tile(t + 2, (t + 2) % 3);
        asm volatile("cp.async.commit_group;");

        const float4* pa = (const float4*)(smem + (t % 3) * (2 * TILEPF));
        const float4* pb = pa + 512;

        float4 afv[2][4], bfv[2][4];
#pragma unroll
        for (int kq = 0; kq < 2; kq++) {
#pragma unroll
            for (int mt = 0; mt < 4; mt++)
                afv[kq][mt] = pa[((wmB + mt) * 2 + kq) * 32 + lane];
#pragma unroll
            for (int np = 0; np < 4; np++)
                bfv[kq][np] = pb[((wnB + np) * 2 + kq) * 32 + lane];
        }
#pragma unroll
        for (int kq = 0; kq < 2; kq++)
#pragma unroll
            for (int mt = 0; mt < 4; mt++)
#pragma unroll
                for (int np = 0; np < 4; np++) {
                    // even nt fragment = (x, z); odd nt fragment = (y, w)
                    asm volatile(
                        "mma.sync.aligned.m16n8k8.row.col.f32.tf32.tf32.f32 "
                        "{%0,%1,%2,%3}, {%4,%5,%6,%7}, {%8,%9}, {%0,%1,%2,%3};"
                        : "+f"(acc[mt][2 * np][0]), "+f"(acc[mt][2 * np][1]),
                          "+f"(acc[mt][2 * np][2]), "+f"(acc[mt][2 * np][3])
                        : "r"(__float_as_uint(afv[kq][mt].x)),
                          "r"(__float_as_uint(afv[kq][mt].y)),
                          "r"(__float_as_uint(afv[kq][mt].z)),
                          "r"(__float_as_uint(afv[kq][mt].w)),
                          "r"(__float_as_uint(bfv[kq][np].x)),
                          "r"(__float_as_uint(bfv[kq][np].z)));
                    asm volatile(
                        "mma.sync.aligned.m16n8k8.row.col.f32.tf32.tf32.f32 "
                        "{%0,%1,%2,%3}, {%4,%5,%6,%7}, {%8,%9}, {%0,%1,%2,%3};"
                        : "+f"(acc[mt][2 * np + 1][0]), "+f"(acc[mt][2 * np + 1][1]),
                          "+f"(acc[mt][2 * np + 1][2]), "+f"(acc[mt][2 * np + 1][3])
                        : "r"(__float_as_uint(afv[kq][mt].x)),
                          "r"(__float_as_uint(afv[kq][mt].y)),
                          "r"(__float_as_uint(afv[kq][mt].z)),
                          "r"(__float_as_uint(afv[kq][mt].w)),
                          "r"(__float_as_uint(bfv[kq][np].y)),
                          "r"(__float_as_uint(bfv[kq][np].w)));
                }
    }

    // epilogue: register -> gmem (normal layout) with bias
    const int r = lane >> 2;
    const int c = lane & 3;
    const int gRow = blockIdx.y * 128 + wmB * 16;
    const int gCol = blockIdx.x * 128 + wnB * 16;
#pragma unroll
    for (int nt = 0; nt < 8; nt++) {
        int col = gCol + nt * 8 + 2 * c;
        float2 bv = *(const float2*)(bias + col);
#pragma unroll
        for (int mt = 0; mt < 4; mt++) {
            int row = gRow + mt * 16 + r;
            float2 o0 = make_float2(acc[mt][nt][0] + bv.x, acc[mt][nt][1] + bv.y);
            *(float2*)(C + (size_t)row * 1024 + col) = o0;
            float2 o1 = make_float2(acc[mt][nt][2] + bv.x, acc[mt][nt][3] + bv.y);
            *(float2*)(C + (size_t)(row + 8) * 1024 + col) = o1;
        }
    }
}

// ---------------- banded A-apply + SELU, sliding window ----------------------
// MODE 0: store selu, tf32-rounded, PERMUTED layout (feeds GEMM2 A-operand).
// MODE 1: emit per-tile column partial sums only (for mean pool).
template <int MODE>
__global__ __launch_bounds__(256)
void banded_win_kernel(const float* __restrict__ H, float* __restrict__ out,
                       const float* __restrict__ fw, const float* __restrict__ bw,
                       const float* __restrict__ dinv) {
    __shared__ float sdv[48];
    __shared__ float scf[FW], scb[BW];
    const int tid = threadIdx.x;
    const int col = blockIdx.y * 256 + tid;
    const int r0  = blockIdx.x * 32;

    if (tid < 48) {
        int row = r0 - 8 + tid;
        sdv[tid] = (row >= 0 && row < NN) ? dinv[row] : 0.0f;
    } else if (tid < 56) scf[tid - 48] = fw[tid - 48];
    else if (tid < 64)   scb[tid - 56] = bw[tid - 56];
    __syncthreads();

    float hs[48];
#pragma unroll
    for (int w = 0; w < 48; w++) {
        int row = r0 - 8 + w;
        hs[w] = (row >= 0 && row < NN)
              ? H[(size_t)row * GC1 + col] * sdv[w] : 0.0f;
    }

    float psum = 0.0f;
#pragma unroll
    for (int i = 0; i < 32; i++) {
        float acc = hs[i + 8];
#pragma unroll
        for (int j = 1; j <= 8; j++) {
            acc = fmaf(scf[j - 1], hs[i + 8 + j], acc);
            acc = fmaf(scb[j - 1], hs[i + 8 - j], acc);
        }
        float v = selu_f(sdv[i + 8] * acc);
        if (MODE == 0) {
            out[perm_fidx(r0 + i, col)] = to_tf32(v);
        } else {
            psum += v;
        }
    }
    if (MODE == 1)
        out[(size_t)blockIdx.x * GC1 + col] = psum;   // out = g_part
}

// ---------------- pool reduce (128 partials) ---------------------------------
__global__ __launch_bounds__(256)
void meanpool2_kernel(const float* __restrict__ part, float* __restrict__ pooled) {
    int col = blockIdx.x * 256 + threadIdx.x;
    float s = 0.f;
#pragma unroll 8
    for (int p = 0; p < 128; p++)
        s += part[(size_t)p * GC2 + col];
    pooled[col] = s * (1.0f / NN);
}

// ---------------- FC head: split-K partials + reduce -------------------------
__global__ __launch_bounds__(512)
void head1_kernel(const float* __restrict__ pooled, const float* __restrict__ w1,
                  float* __restrict__ zpart) {
    int j = threadIdx.x;
    int c0 = blockIdx.x * 64;
    float s = 0.f;
#pragma unroll 8
    for (int c = 0; c < 64; c++)
        s = fmaf(pooled[c0 + c], w1[(size_t)(c0 + c) * FC1 + j], s);
    zpart[blockIdx.x * FC1 + j] = s;
}

__global__ __launch_bounds__(512)
void head2_kernel(const float* __restrict__ zpart,
                  const float* __restrict__ b1,
                  const float* __restrict__ w2, const float* __restrict__ b2,
                  float* __restrict__ out) {
    __shared__ float z[FC1];
    __shared__ float p0s[64], p1s[64];
    int j = threadIdx.x;

    float s = b1[j];
#pragma unroll
    for (int b = 0; b < 16; b++)
        s += zpart[b * FC1 + j];
    z[j] = selu_f(s);
    __syncthreads();

    if (j < 64) {
        float a0 = 0.f, a1 = 0.f;
        for (int t = j; t < FC1; t += 64) {
            a0 = fmaf(z[t], w2[t * NCLS + 0], a0);
            a1 = fmaf(z[t], w2[t * NCLS + 1], a1);
        }
        p0s[j] = a0; p1s[j] = a1;
    }
    __syncthreads();

    if (j == 0) {
        float a0 = b2[0], a1 = b2[1];
        for (int t = 0; t < 64; t++) { a0 += p0s[t]; a1 += p1s[t]; }
        out[0] = a0; out[1] = a1;
    }
}

// ---------------- launch -----------------------------------------------------
extern "C" void kernel_launch(void* const* d_in, const int* in_sizes, int n_in,
                              void* d_out, int out_size) {
    const float* x     = (const float*)d_in[0];
    const float* fw_w  = (const float*)d_in[1];
    const float* bw_w  = (const float*)d_in[2];
    const float* gc_w1 = (const float*)d_in[3];
    const float* gc_b1 = (const float*)d_in[4];
    const float* gc_w2 = (const float*)d_in[5];
    const float* gc_b2 = (const float*)d_in[6];
    const float* fc_w1 = (const float*)d_in[7];
    const float* fc_b1 = (const float*)d_in[8];
    const float* fc_w2 = (const float*)d_in[9];
    const float* fc_b2 = (const float*)d_in[10];
    float* out = (float*)d_out;

    float *bufA, *bufB, *bufX, *wT, *dinv, *pooled, *part, *zpart;
    cudaGetSymbolAddress((void**)&bufA,   g_bufA);
    cudaGetSymbolAddress((void**)&bufB,   g_bufB);
    cudaGetSymbolAddress((void**)&bufX,   g_bufX);
    cudaGetSymbolAddress((void**)&wT,     g_wT);
    cudaGetSymbolAddress((void**)&dinv,   g_dinv);
    cudaGetSymbolAddress((void**)&pooled, g_pooled);
    cudaGetSymbolAddress((void**)&part,   g_part);
    cudaGetSymbolAddress((void**)&zpart,  g_zpart);

    cudaFuncSetAttribute(tf32_mma_gemm,
                         cudaFuncAttributeMaxDynamicSharedMemorySize, GEMM_SMEM);

    degrees_kernel<<<(NN + 255) / 256, 256>>>(fw_w, bw_w, dinv);

    dim3 tgrid(32, 32);
    dim3 ggrid(GC1 / 128, NN / 128);     // (8, 32)
    dim3 bgrid(NN / 32, GC1 / 256);      // (128, 4)

    permX_kernel<<<4096, 256>>>(x, bufX);

    // layer 1
    permW_kernel<<<tgrid, 256>>>(gc_w1, wT);
    tf32_mma_gemm<<<ggrid, 128, GEMM_SMEM>>>(bufX, wT, gc_b1, bufA);
    banded_win_kernel<0><<<bgrid, 256>>>(bufA, bufB, fw_w, bw_w, dinv);

    // layer 2 (banded output fused into pool partials)
    permW_kernel<<<tgrid, 256>>>(gc_w2, wT);
    tf32_mma_gemm<<<ggrid, 128, GEMM_SMEM>>>(bufB, wT, gc_b2, bufA);
    banded_win_kernel<1><<<bgrid, 256>>>(bufA, part, fw_w, bw_w, dinv);

    // pool + head
    meanpool2_kernel<<<4, 256>>>(part, pooled);
    head1_kernel<<<16, FC1>>>(pooled, fc_w1, zpart);
    head2_kernel<<<1, FC1>>>(zpart, fc_b1, fc_w2, fc_b2, out);
}